// round 4
// baseline (speedup 1.0000x reference)
#include <cuda_runtime.h>

#define B 4
#define L 2048
#define H 8
#define D 64
#define S 40
#define NTOP 40
#define BH (B*H)

#define KS 8            // k-splits for flash attention
#define KC (L/KS)       // 256 keys per split
#define KT 64           // tile rows
#define NTILE (KC/KT)   // 4 tiles per split

#define CCH 64          // cumsum chunks
#define CLEN (L/CCH)    // 32 rows per chunk

// Scratch (no allocations allowed)
__device__ float g_M[BH * L];
__device__ int   g_top[BH * NTOP];
__device__ float g_cs[BH * CCH * D];
__device__ float g_pm[BH * NTOP * KS];
__device__ float g_pl[BH * NTOP * KS];
__device__ float g_pacc[BH * NTOP * KS * D];

// ---------------------------------------------------------------------------
// Kernel 1: M[bh,l] = max_s(Q[l]·K[idx[l,s]]) - (sum_s Q[l]·K[idx[l,s]]) / L
// One warp per (bh,l); lane per sample, full dot per lane (MLP=16).
// index_sample is int32 on the wire (JAX x64-disabled downcasts int64).
// ---------------------------------------------------------------------------
__global__ void mscore_kernel(const float* __restrict__ Q,
                              const float* __restrict__ K,
                              const int* __restrict__ idx) {
    int warp = blockIdx.x * 4 + (threadIdx.x >> 5);
    int lane = threadIdx.x & 31;
    int wl   = threadIdx.x >> 5;
    int l  = warp & (L - 1);
    int bh = warp >> 11;
    int b = bh >> 3, h = bh & 7;

    __shared__ float4 qs[4][16];
    const float4* qrow = (const float4*)(Q + ((size_t)(b * L + l) * H + h) * D);
    if (lane < 16) qs[wl][lane] = qrow[lane];
    __syncwarp();

    const int* srow = idx + (size_t)l * S;
    float mx = -1e30f, sm = 0.f;

    #pragma unroll
    for (int s0 = 0; s0 < S; s0 += 32) {
        int s = s0 + lane;
        float dot = -1e30f, dsum = 0.f;
        if (s < S) {
            int ki = srow[s];
            const float4* krow = (const float4*)(K + ((size_t)(b * L + ki) * H + h) * D);
            float d = 0.f;
            #pragma unroll
            for (int j = 0; j < 16; j++) {
                float4 kv = krow[j], qv = qs[wl][j];
                d += qv.x*kv.x + qv.y*kv.y + qv.z*kv.z + qv.w*kv.w;
            }
            dot = d; dsum = d;
        }
        mx = fmaxf(mx, dot);
        sm += dsum;
    }
    #pragma unroll
    for (int off = 16; off; off >>= 1) {
        mx = fmaxf(mx, __shfl_xor_sync(0xffffffffu, mx, off));
        sm += __shfl_xor_sync(0xffffffffu, sm, off);
    }
    if (lane == 0) g_M[bh * L + l] = mx - sm * (1.0f / (float)L);
}

// ---------------------------------------------------------------------------
// Kernel 2: top-40 indices of M per (bh); 40 sequential block-argmax passes.
// ---------------------------------------------------------------------------
__global__ void topk_kernel() {
    int bh = blockIdx.x;
    __shared__ float vals[L];
    __shared__ float wv[8];
    __shared__ int   wi[8];
    int tid = threadIdx.x;  // 256

    for (int i = tid; i < L; i += 256) vals[i] = g_M[bh * L + i];
    __syncthreads();

    for (int t = 0; t < NTOP; t++) {
        float bv = -1e38f; int bi = 0;
        for (int i = tid; i < L; i += 256) {
            float v = vals[i];
            if (v > bv) { bv = v; bi = i; }
        }
        #pragma unroll
        for (int off = 16; off; off >>= 1) {
            float ov = __shfl_down_sync(0xffffffffu, bv, off);
            int   oi = __shfl_down_sync(0xffffffffu, bi, off);
            if (ov > bv || (ov == bv && oi < bi)) { bv = ov; bi = oi; }
        }
        if ((tid & 31) == 0) { wv[tid >> 5] = bv; wi[tid >> 5] = bi; }
        __syncthreads();
        if (tid == 0) {
            float fv = wv[0]; int fi = wi[0];
            #pragma unroll
            for (int w = 1; w < 8; w++)
                if (wv[w] > fv || (wv[w] == fv && wi[w] < fi)) { fv = wv[w]; fi = wi[w]; }
            g_top[bh * NTOP + t] = fi;
            vals[fi] = -1e38f;
        }
        __syncthreads();
    }
}

// ---------------------------------------------------------------------------
// Kernel 3a: per-chunk sums of V over l.  grid (CCH, BH), block D.
// ---------------------------------------------------------------------------
__global__ void cumsumA_kernel(const float* __restrict__ V) {
    int c = blockIdx.x, bh = blockIdx.y;
    int b = bh >> 3, h = bh & 7;
    int d = threadIdx.x;
    const float* vb = V + ((size_t)(b * L + c * CLEN) * H + h) * D + d;
    float s = 0.f;
    #pragma unroll
    for (int i = 0; i < CLEN; i++) s += vb[(size_t)i * H * D];
    g_cs[(bh * CCH + c) * D + d] = s;
}

// ---------------------------------------------------------------------------
// Kernel 3b: each chunk sums preceding chunk-sums, then scans its 32 rows.
// ---------------------------------------------------------------------------
__global__ void cumsumC_kernel(const float* __restrict__ V, float* __restrict__ out) {
    int c = blockIdx.x, bh = blockIdx.y;
    int b = bh >> 3, h = bh & 7;
    int d = threadIdx.x;
    float run = 0.f;
    for (int cc = 0; cc < c; cc++) run += g_cs[(bh * CCH + cc) * D + d];
    const float* vb = V + ((size_t)(b * L + c * CLEN) * H + h) * D + d;
    float* ob = out + ((size_t)bh * L + c * CLEN) * D + d;
    #pragma unroll
    for (int i = 0; i < CLEN; i++) {
        run += vb[(size_t)i * H * D];
        ob[(size_t)i * D] = run;
    }
}

// ---------------------------------------------------------------------------
// Kernel 4: flash attention partials. grid (KS, BH), block 256 (8 warps).
// Warp w owns u-rows [5w, 5w+5). Lane handles t0=lane, t1=lane+32 of each
// 64-row K/V tile (transposed, pad-65, conflict-free) and d=lane, lane+32
// of the output accumulator.
// ---------------------------------------------------------------------------
__global__ void __launch_bounds__(256)
attn_flash_kernel(const float* __restrict__ Q,
                  const float* __restrict__ K,
                  const float* __restrict__ V) {
    int ks = blockIdx.x, bh = blockIdx.y;
    int b = bh >> 3, h = bh & 7;
    int tid = threadIdx.x, w = tid >> 5, lane = tid & 31;
    int u0 = w * 5;
    int kbase0 = ks * KC;

    __shared__ float  tileT[D][KT + 1];     // K then V, transposed [d][t]
    __shared__ float4 qs4[NTOP][16];
    __shared__ float4 ps4[NTOP][16];
    __shared__ int    lus[NTOP];

    if (tid < NTOP) lus[tid] = g_top[bh * NTOP + tid];
    __syncthreads();
    for (int i = tid; i < NTOP * 16; i += 256) {
        int u = i >> 4, cq = i & 15;
        qs4[u][cq] = ((const float4*)(Q + ((size_t)(b * L + lus[u]) * H + h) * D))[cq];
    }

    float m[5], lsum[5], acc0[5], acc1[5];
    #pragma unroll
    for (int iu = 0; iu < 5; iu++) { m[iu] = -1e30f; lsum[iu] = 0.f; acc0[iu] = 0.f; acc1[iu] = 0.f; }

    int lr = tid >> 2, lc = tid & 3;   // tile-load: row, float4-lane
    float* psf = (float*)ps4;
    int t0 = lane, t1 = lane + 32;

    for (int tt = 0; tt < NTILE; tt++) {
        int kbase = kbase0 + tt * KT;

        __syncthreads();   // previous tile fully consumed (also covers qs on tt=0)
        {   // K tile -> tileT
            const float4* kr = (const float4*)(K + ((size_t)(b * L + kbase + lr) * H + h) * D);
            #pragma unroll
            for (int j = 0; j < 4; j++) {
                float4 v = kr[lc + 4 * j];
                int dc = (lc + 4 * j) * 4;
                tileT[dc + 0][lr] = v.x; tileT[dc + 1][lr] = v.y;
                tileT[dc + 2][lr] = v.z; tileT[dc + 3][lr] = v.w;
            }
        }
        __syncthreads();

        // scores: 5u x 2t register tile
        float s0[5], s1[5];
        #pragma unroll
        for (int iu = 0; iu < 5; iu++) { s0[iu] = 0.f; s1[iu] = 0.f; }
        #pragma unroll
        for (int d4 = 0; d4 < 16; d4++) {
            float k00 = tileT[d4*4+0][t0], k01 = tileT[d4*4+1][t0];
            float k02 = tileT[d4*4+2][t0], k03 = tileT[d4*4+3][t0];
            float k10 = tileT[d4*4+0][t1], k11 = tileT[d4*4+1][t1];
            float k12 = tileT[d4*4+2][t1], k13 = tileT[d4*4+3][t1];
            #pragma unroll
            for (int iu = 0; iu < 5; iu++) {
                float4 q = qs4[u0 + iu][d4];
                s0[iu] += q.x*k00 + q.y*k01 + q.z*k02 + q.w*k03;
                s1[iu] += q.x*k10 + q.y*k11 + q.z*k12 + q.w*k13;
            }
        }

        // streaming softmax update
        int kg0 = kbase + t0, kg1 = kbase + t1;
        #pragma unroll
        for (int iu = 0; iu < 5; iu++) {
            int lu = lus[u0 + iu];
            float a = (kg0 <= lu) ? s0[iu] * 0.125f : -3e38f;
            float c = (kg1 <= lu) ? s1[iu] * 0.125f : -3e38f;
            float mt = fmaxf(a, c);
            #pragma unroll
            for (int off = 16; off; off >>= 1)
                mt = fmaxf(mt, __shfl_xor_sync(0xffffffffu, mt, off));
            float mn = fmaxf(m[iu], mt);
            float f  = __expf(m[iu] - mn);
            float p0 = __expf(a - mn), p1 = __expf(c - mn);
            float psum = p0 + p1;
            #pragma unroll
            for (int off = 16; off; off >>= 1)
                psum += __shfl_xor_sync(0xffffffffu, psum, off);
            lsum[iu] = lsum[iu] * f + psum;
            acc0[iu] *= f; acc1[iu] *= f;
            psf[(u0 + iu) * 64 + t0] = p0;
            psf[(u0 + iu) * 64 + t1] = p1;
            m[iu] = mn;
        }
        __syncwarp();
        __syncthreads();   // scores done reading tileT

        {   // V tile -> tileT
            const float4* vr = (const float4*)(V + ((size_t)(b * L + kbase + lr) * H + h) * D);
            #pragma unroll
            for (int j = 0; j < 4; j++) {
                float4 v = vr[lc + 4 * j];
                int dc = (lc + 4 * j) * 4;
                tileT[dc + 0][lr] = v.x; tileT[dc + 1][lr] = v.y;
                tileT[dc + 2][lr] = v.z; tileT[dc + 3][lr] = v.w;
            }
        }
        __syncthreads();

        // accumulate p * V   (d = lane, lane+32)
        #pragma unroll
        for (int t4 = 0; t4 < 16; t4++) {
            float v00 = tileT[lane][t4*4+0], v01 = tileT[lane][t4*4+1];
            float v02 = tileT[lane][t4*4+2], v03 = tileT[lane][t4*4+3];
            float v10 = tileT[lane+32][t4*4+0], v11 = tileT[lane+32][t4*4+1];
            float v12 = tileT[lane+32][t4*4+2], v13 = tileT[lane+32][t4*4+3];
            #pragma unroll
            for (int iu = 0; iu < 5; iu++) {
                float4 p = ps4[u0 + iu][t4];
                acc0[iu] += p.x*v00 + p.y*v01 + p.z*v02 + p.w*v03;
                acc1[iu] += p.x*v10 + p.y*v11 + p.z*v12 + p.w*v13;
            }
        }
    }

    // write partials
    #pragma unroll
    for (int iu = 0; iu < 5; iu++) {
        size_t base = (size_t)(bh * NTOP + u0 + iu) * KS + ks;
        g_pacc[base * D + lane]      = acc0[iu];
        g_pacc[base * D + lane + 32] = acc1[iu];
        if (lane == 0) { g_pm[base] = m[iu]; g_pl[base] = lsum[iu]; }
    }
}

// ---------------------------------------------------------------------------
// Kernel 5: combine KS partials per (bh,u), normalize, scatter into out.
// ---------------------------------------------------------------------------
__global__ void attn_combine_kernel(float* __restrict__ out) {
    int u = blockIdx.x, bh = blockIdx.y;
    int d = threadIdx.x;
    size_t base = (size_t)(bh * NTOP + u) * KS;

    float mv[KS], lv[KS];
    float mg = -3e38f;
    #pragma unroll
    for (int p = 0; p < KS; p++) {
        mv[p] = g_pm[base + p];
        lv[p] = g_pl[base + p];
        mg = fmaxf(mg, mv[p]);
    }
    float ltot = 0.f, acc = 0.f;
    #pragma unroll
    for (int p = 0; p < KS; p++) {
        float e = __expf(mv[p] - mg);
        ltot += lv[p] * e;
        acc  += g_pacc[(base + p) * D + d] * e;
    }
    int lu = g_top[bh * NTOP + u];
    out[((size_t)bh * L + lu) * D + d] = acc / ltot;
}

// ---------------------------------------------------------------------------
extern "C" void kernel_launch(void* const* d_in, const int* in_sizes, int n_in,
                              void* d_out, int out_size) {
    const float* Q   = (const float*)d_in[0];
    const float* K   = (const float*)d_in[1];
    const float* V   = (const float*)d_in[2];
    const int*   idx = (const int*)d_in[3];
    float*       out = (float*)d_out;

    mscore_kernel<<<BH * L / 4, 128>>>(Q, K, idx);
    topk_kernel  <<<BH, 256>>>();
    cumsumA_kernel<<<dim3(CCH, BH), D>>>(V);
    cumsumC_kernel<<<dim3(CCH, BH), D>>>(V, out);
    attn_flash_kernel<<<dim3(KS, BH), 256>>>(Q, K, V);
    attn_combine_kernel<<<dim3(NTOP, BH), D>>>(out);
}

// round 5
// speedup vs baseline: 2.0560x; 2.0560x over previous
#include <cuda_runtime.h>

#define B 4
#define L 2048
#define H 8
#define D 64
#define S 40
#define NTOP 40
#define BH (B*H)

#define KS 8            // k-splits for flash attention
#define KC (L/KS)       // 256 keys per split
#define KT 64           // tile rows
#define NTILE (KC/KT)   // 4 tiles per split

#define CCH 64          // cumsum chunks
#define CLEN (L/CCH)    // 32 rows per chunk

#define FULLMASK 0xffffffffu

// Scratch (no allocations allowed)
__device__ float g_M[BH * L];
__device__ int   g_top[BH * NTOP];
__device__ float g_cs[BH * CCH * D];
__device__ float g_pm[BH * NTOP * KS];
__device__ float g_pl[BH * NTOP * KS];
__device__ float g_pacc[BH * NTOP * KS * D];

// ---------------------------------------------------------------------------
// Kernel 1: M[bh,l] = max_s(Q[l]·K[idx[l,s]]) - (sum_s Q[l]·K[idx[l,s]]) / L
// One warp per (bh,l). COALESCED group-gather: 8 lanes per sample, 4 samples
// per step, 10 steps. Each LDG.128 covers 128 contiguous bytes in each of 4
// K rows (nL=4 wavefronts vs 32 for lane-per-sample). Sample indices are
// preloaded per-warp and distributed by shuffle. index_sample is int32 on
// the wire (JAX x64-disabled downcasts int64).
// ---------------------------------------------------------------------------
__global__ void __launch_bounds__(256)
mscore_kernel(const float* __restrict__ Q,
              const float* __restrict__ K,
              const int* __restrict__ idx) {
    int warp = blockIdx.x * 8 + (threadIdx.x >> 5);
    int lane = threadIdx.x & 31;
    int g = lane >> 3, j = lane & 7;
    int l  = warp & (L - 1);
    int bh = warp >> 11;
    int b = bh >> 3, h = bh & 7;

    // q slice for this lane: floats [4j..4j+3] and [32+4j..32+4j+3]
    const float4* q4 = (const float4*)(Q + ((size_t)(b * L + l) * H + h) * D);
    float4 qa = q4[j], qb = q4[8 + j];

    // preload sample indices (40 of them) into two per-lane registers
    const int* srow = idx + (size_t)l * S;
    int s_lo = (lane < 32) ? srow[lane] : 0;
    int s_hi = (lane < 8)  ? srow[lane + 32] : 0;

    const float* Kb = K + ((size_t)b * L * H + h) * D;
    float mx = -1e30f, sm = 0.f;

    #pragma unroll
    for (int bt = 0; bt < 10; bt++) {
        int s = bt * 4 + g;                       // 0..39, compile-time branch below
        int ki = (bt < 8) ? __shfl_sync(FULLMASK, s_lo, s)
                          : __shfl_sync(FULLMASK, s_hi, s - 32);
        const float4* k4 = (const float4*)(Kb + (size_t)ki * H * D);
        float4 ka = k4[j], kb = k4[8 + j];
        float d = qa.x*ka.x + qa.y*ka.y + qa.z*ka.z + qa.w*ka.w
                + qb.x*kb.x + qb.y*kb.y + qb.z*kb.z + qb.w*kb.w;
        d += __shfl_down_sync(FULLMASK, d, 4);
        d += __shfl_down_sync(FULLMASK, d, 2);
        d += __shfl_down_sync(FULLMASK, d, 1);
        if (j == 0) { mx = fmaxf(mx, d); sm += d; }   // valid at lanes 0,8,16,24
    }

    // combine the 4 group leaders (lanes 0,8,16,24 differ in bits 3,4)
    if (j != 0) { mx = -1e30f; sm = 0.f; }
    mx = fmaxf(mx, __shfl_xor_sync(FULLMASK, mx, 8));
    sm +=          __shfl_xor_sync(FULLMASK, sm, 8);
    mx = fmaxf(mx, __shfl_xor_sync(FULLMASK, mx, 16));
    sm +=          __shfl_xor_sync(FULLMASK, sm, 16);

    if (lane == 0) g_M[bh * L + l] = mx - sm * (1.0f / (float)L);
}

// ---------------------------------------------------------------------------
// Kernel 2: top-40 indices of M per (bh); 40 sequential block-argmax passes.
// ---------------------------------------------------------------------------
__global__ void topk_kernel() {
    int bh = blockIdx.x;
    __shared__ float vals[L];
    __shared__ float wv[8];
    __shared__ int   wi[8];
    int tid = threadIdx.x;  // 256

    for (int i = tid; i < L; i += 256) vals[i] = g_M[bh * L + i];
    __syncthreads();

    for (int t = 0; t < NTOP; t++) {
        float bv = -1e38f; int bi = 0;
        for (int i = tid; i < L; i += 256) {
            float v = vals[i];
            if (v > bv) { bv = v; bi = i; }
        }
        #pragma unroll
        for (int off = 16; off; off >>= 1) {
            float ov = __shfl_down_sync(FULLMASK, bv, off);
            int   oi = __shfl_down_sync(FULLMASK, bi, off);
            if (ov > bv || (ov == bv && oi < bi)) { bv = ov; bi = oi; }
        }
        if ((tid & 31) == 0) { wv[tid >> 5] = bv; wi[tid >> 5] = bi; }
        __syncthreads();
        if (tid == 0) {
            float fv = wv[0]; int fi = wi[0];
            #pragma unroll
            for (int w = 1; w < 8; w++)
                if (wv[w] > fv || (wv[w] == fv && wi[w] < fi)) { fv = wv[w]; fi = wi[w]; }
            g_top[bh * NTOP + t] = fi;
            vals[fi] = -1e38f;
        }
        __syncthreads();
    }
}

// ---------------------------------------------------------------------------
// Kernel 3a: per-chunk sums of V over l.  grid (CCH, BH), block D.
// ---------------------------------------------------------------------------
__global__ void cumsumA_kernel(const float* __restrict__ V) {
    int c = blockIdx.x, bh = blockIdx.y;
    int b = bh >> 3, h = bh & 7;
    int d = threadIdx.x;
    const float* vb = V + ((size_t)(b * L + c * CLEN) * H + h) * D + d;
    float s = 0.f;
    #pragma unroll
    for (int i = 0; i < CLEN; i++) s += vb[(size_t)i * H * D];
    g_cs[(bh * CCH + c) * D + d] = s;
}

// ---------------------------------------------------------------------------
// Kernel 3b: each chunk sums preceding chunk-sums, then scans its 32 rows.
// Loads staged into registers first to decouple latency from the scan chain.
// ---------------------------------------------------------------------------
__global__ void cumsumC_kernel(const float* __restrict__ V, float* __restrict__ out) {
    int c = blockIdx.x, bh = blockIdx.y;
    int b = bh >> 3, h = bh & 7;
    int d = threadIdx.x;

    const float* vb = V + ((size_t)(b * L + c * CLEN) * H + h) * D + d;
    float v[CLEN];
    #pragma unroll
    for (int i = 0; i < CLEN; i++) v[i] = vb[(size_t)i * H * D];

    float run = 0.f;
    for (int cc = 0; cc < c; cc++) run += g_cs[(bh * CCH + cc) * D + d];

    float* ob = out + ((size_t)bh * L + c * CLEN) * D + d;
    #pragma unroll
    for (int i = 0; i < CLEN; i++) {
        run += v[i];
        ob[(size_t)i * D] = run;
    }
}

// ---------------------------------------------------------------------------
// Kernel 4: flash attention partials. grid (KS, BH), block 256 (8 warps).
// Warp w owns u-rows [5w, 5w+5). Lane handles t0=lane, t1=lane+32 of each
// 64-row K/V tile (transposed, pad-65, conflict-free) and d=lane, lane+32
// of the output accumulator.
// ---------------------------------------------------------------------------
__global__ void __launch_bounds__(256)
attn_flash_kernel(const float* __restrict__ Q,
                  const float* __restrict__ K,
                  const float* __restrict__ V) {
    int ks = blockIdx.x, bh = blockIdx.y;
    int b = bh >> 3, h = bh & 7;
    int tid = threadIdx.x, w = tid >> 5, lane = tid & 31;
    int u0 = w * 5;
    int kbase0 = ks * KC;

    __shared__ float  tileT[D][KT + 1];     // K then V, transposed [d][t]
    __shared__ float4 qs4[NTOP][16];
    __shared__ float4 ps4[NTOP][16];
    __shared__ int    lus[NTOP];

    if (tid < NTOP) lus[tid] = g_top[bh * NTOP + tid];
    __syncthreads();
    for (int i = tid; i < NTOP * 16; i += 256) {
        int u = i >> 4, cq = i & 15;
        qs4[u][cq] = ((const float4*)(Q + ((size_t)(b * L + lus[u]) * H + h) * D))[cq];
    }

    float m[5], lsum[5], acc0[5], acc1[5];
    #pragma unroll
    for (int iu = 0; iu < 5; iu++) { m[iu] = -1e30f; lsum[iu] = 0.f; acc0[iu] = 0.f; acc1[iu] = 0.f; }

    int lr = tid >> 2, lc = tid & 3;   // tile-load: row, float4-lane
    float* psf = (float*)ps4;
    int t0 = lane, t1 = lane + 32;

    for (int tt = 0; tt < NTILE; tt++) {
        int kbase = kbase0 + tt * KT;

        __syncthreads();   // previous tile fully consumed (also covers qs on tt=0)
        {   // K tile -> tileT
            const float4* kr = (const float4*)(K + ((size_t)(b * L + kbase + lr) * H + h) * D);
            #pragma unroll
            for (int j = 0; j < 4; j++) {
                float4 v = kr[lc + 4 * j];
                int dc = (lc + 4 * j) * 4;
                tileT[dc + 0][lr] = v.x; tileT[dc + 1][lr] = v.y;
                tileT[dc + 2][lr] = v.z; tileT[dc + 3][lr] = v.w;
            }
        }
        __syncthreads();

        // scores: 5u x 2t register tile
        float s0[5], s1[5];
        #pragma unroll
        for (int iu = 0; iu < 5; iu++) { s0[iu] = 0.f; s1[iu] = 0.f; }
        #pragma unroll
        for (int d4 = 0; d4 < 16; d4++) {
            float k00 = tileT[d4*4+0][t0], k01 = tileT[d4*4+1][t0];
            float k02 = tileT[d4*4+2][t0], k03 = tileT[d4*4+3][t0];
            float k10 = tileT[d4*4+0][t1], k11 = tileT[d4*4+1][t1];
            float k12 = tileT[d4*4+2][t1], k13 = tileT[d4*4+3][t1];
            #pragma unroll
            for (int iu = 0; iu < 5; iu++) {
                float4 q = qs4[u0 + iu][d4];
                s0[iu] += q.x*k00 + q.y*k01 + q.z*k02 + q.w*k03;
                s1[iu] += q.x*k10 + q.y*k11 + q.z*k12 + q.w*k13;
            }
        }

        // streaming softmax update
        int kg0 = kbase + t0, kg1 = kbase + t1;
        #pragma unroll
        for (int iu = 0; iu < 5; iu++) {
            int lu = lus[u0 + iu];
            float a = (kg0 <= lu) ? s0[iu] * 0.125f : -3e38f;
            float c = (kg1 <= lu) ? s1[iu] * 0.125f : -3e38f;
            float mt = fmaxf(a, c);
            #pragma unroll
            for (int off = 16; off; off >>= 1)
                mt = fmaxf(mt, __shfl_xor_sync(FULLMASK, mt, off));
            float mn = fmaxf(m[iu], mt);
            float f  = __expf(m[iu] - mn);
            float p0 = __expf(a - mn), p1 = __expf(c - mn);
            float psum = p0 + p1;
            #pragma unroll
            for (int off = 16; off; off >>= 1)
                psum += __shfl_xor_sync(FULLMASK, psum, off);
            lsum[iu] = lsum[iu] * f + psum;
            acc0[iu] *= f; acc1[iu] *= f;
            psf[(u0 + iu) * 64 + t0] = p0;
            psf[(u0 + iu) * 64 + t1] = p1;
            m[iu] = mn;
        }
        __syncwarp();
        __syncthreads();   // scores done reading tileT

        {   // V tile -> tileT
            const float4* vr = (const float4*)(V + ((size_t)(b * L + kbase + lr) * H + h) * D);
            #pragma unroll
            for (int j = 0; j < 4; j++) {
                float4 v = vr[lc + 4 * j];
                int dc = (lc + 4 * j) * 4;
                tileT[dc + 0][lr] = v.x; tileT[dc + 1][lr] = v.y;
                tileT[dc + 2][lr] = v.z; tileT[dc + 3][lr] = v.w;
            }
        }
        __syncthreads();

        // accumulate p * V   (d = lane, lane+32)
        #pragma unroll
        for (int t4 = 0; t4 < 16; t4++) {
            float v00 = tileT[lane][t4*4+0], v01 = tileT[lane][t4*4+1];
            float v02 = tileT[lane][t4*4+2], v03 = tileT[lane][t4*4+3];
            float v10 = tileT[lane+32][t4*4+0], v11 = tileT[lane+32][t4*4+1];
            float v12 = tileT[lane+32][t4*4+2], v13 = tileT[lane+32][t4*4+3];
            #pragma unroll
            for (int iu = 0; iu < 5; iu++) {
                float4 p = ps4[u0 + iu][t4];
                acc0[iu] += p.x*v00 + p.y*v01 + p.z*v02 + p.w*v03;
                acc1[iu] += p.x*v10 + p.y*v11 + p.z*v12 + p.w*v13;
            }
        }
    }

    // write partials
    #pragma unroll
    for (int iu = 0; iu < 5; iu++) {
        size_t base = (size_t)(bh * NTOP + u0 + iu) * KS + ks;
        g_pacc[base * D + lane]      = acc0[iu];
        g_pacc[base * D + lane + 32] = acc1[iu];
        if (lane == 0) { g_pm[base] = m[iu]; g_pl[base] = lsum[iu]; }
    }
}

// ---------------------------------------------------------------------------
// Kernel 5: combine KS partials per (bh,u), normalize, scatter into out.
// ---------------------------------------------------------------------------
__global__ void attn_combine_kernel(float* __restrict__ out) {
    int u = blockIdx.x, bh = blockIdx.y;
    int d = threadIdx.x;
    size_t base = (size_t)(bh * NTOP + u) * KS;

    float mv[KS], lv[KS];
    float mg = -3e38f;
    #pragma unroll
    for (int p = 0; p < KS; p++) {
        mv[p] = g_pm[base + p];
        lv[p] = g_pl[base + p];
        mg = fmaxf(mg, mv[p]);
    }
    float ltot = 0.f, acc = 0.f;
    #pragma unroll
    for (int p = 0; p < KS; p++) {
        float e = __expf(mv[p] - mg);
        ltot += lv[p] * e;
        acc  += g_pacc[(base + p) * D + d] * e;
    }
    int lu = g_top[bh * NTOP + u];
    out[((size_t)bh * L + lu) * D + d] = acc / ltot;
}

// ---------------------------------------------------------------------------
extern "C" void kernel_launch(void* const* d_in, const int* in_sizes, int n_in,
                              void* d_out, int out_size) {
    const float* Q   = (const float*)d_in[0];
    const float* K   = (const float*)d_in[1];
    const float* V   = (const float*)d_in[2];
    const int*   idx = (const int*)d_in[3];
    float*       out = (float*)d_out;

    mscore_kernel<<<BH * L / 8, 256>>>(Q, K, idx);
    topk_kernel  <<<BH, 256>>>();
    cumsumA_kernel<<<dim3(CCH, BH), D>>>(V);
    cumsumC_kernel<<<dim3(CCH, BH), D>>>(V, out);
    attn_flash_kernel<<<dim3(KS, BH), 256>>>(Q, K, V);
    attn_combine_kernel<<<dim3(NTOP, BH), D>>>(out);
}